// round 3
// baseline (speedup 1.0000x reference)
#include <cuda_runtime.h>

#define NN      64
#define NTYPES  4
#define NDESC   8
#define KMAX    8
#define RC      8.0f
#define PI_F    3.14159265358979323846f
#define MAX_ATOMS 32768

// packed[i] = (pos.x, pos.y, pos.z, bitcast(type))
__device__ float4 g_packed[MAX_ATOMS];

__device__ __forceinline__ float fsqrt_approx(float x) {
    float y; asm("sqrt.approx.f32 %0, %1;" : "=f"(y) : "f"(x)); return y;
}
__device__ __forceinline__ float fcos_approx(float x) {
    float y; asm("cos.approx.f32 %0, %1;" : "=f"(y) : "f"(x)); return y;
}

__global__ void pack_kernel(const int* __restrict__ types,
                            const float* __restrict__ pos, int n)
{
    int i = blockIdx.x * blockDim.x + threadIdx.x;
    if (i < n) {
        float4 p;
        p.x = pos[i * 3 + 0];
        p.y = pos[i * 3 + 1];
        p.z = pos[i * 3 + 2];
        p.w = __int_as_float(types[i]);
        g_packed[i] = p;
    }
}

// 1 atom per warp, 2 edges per lane. 8 warps/block -> 8 atoms/block, grid=2500.
// G[4][8] accumulators reduced by full-warp 5-stage halving butterfly so that
// lane l ends holding total G for (t = l>>3, k = l&7). Per-atom 4x8->8 matvec
// against a TRANSPOSED shared c_table (2x LDS.128 per lane), final butterfly
// lands descriptor d on lane d.
__global__ __launch_bounds__(256, 4) void radial_desc_kernel(
    const int*   __restrict__ nbr,
    const float* __restrict__ offs,
    const float* __restrict__ ctab,
    float*       __restrict__ out,
    int n_atoms)
{
    // transposed: c_sh[((ti*4+t)*8 + k)*8 + d] = ctab[((ti*4+t)*8 + d)*8 + k]
    __shared__ float c_sh[NTYPES * NTYPES * NDESC * KMAX];  // 4 KB
    for (int i = threadIdx.x; i < NTYPES * NTYPES * NDESC * KMAX; i += blockDim.x) {
        const int d = (i >> 3) & 7;
        const int k = i & 7;
        c_sh[(i & ~63) | (k << 3) | d] = ctab[i];
    }
    __syncthreads();

    const int lane = threadIdx.x & 31;
    const int warp = threadIdx.x >> 5;

    const int atom = blockIdx.x * 8 + warp;
    const bool ok  = (atom < n_atoms);
    const int a    = ok ? atom : 0;

    const float4 pa = g_packed[a];
    const int    ti = __float_as_int(pa.w);

    // lane owns edges 2*lane, 2*lane+1
    const int2   nv = __ldcs(reinterpret_cast<const int2*>(nbr) + (long)a * 32 + lane);
    const float2* ob2 = reinterpret_cast<const float2*>(offs) + (long)a * 96 + lane * 3;
    const float2 o0 = __ldcs(ob2 + 0);
    const float2 o1 = __ldcs(ob2 + 1);
    const float2 o2 = __ldcs(ob2 + 2);

    const bool v0 = (nv.x >= 0) && ok;
    const bool v1 = (nv.y >= 0) && ok;
    const float4 P0 = g_packed[v0 ? nv.x : 0];
    const float4 P1 = g_packed[v1 ? nv.y : 0];

    float G[4][8];
    #pragma unroll
    for (int t = 0; t < 4; t++)
        #pragma unroll
        for (int k = 0; k < 8; k++)
            G[t][k] = 0.0f;

    const float eox[2] = { o0.x, o1.y };
    const float eoy[2] = { o0.y, o2.x };
    const float eoz[2] = { o1.x, o2.y };
    const float4 P[2]  = { P0, P1 };
    const bool  vld[2] = { v0, v1 };

    #pragma unroll
    for (int e = 0; e < 2; e++) {
        const float dx = P[e].x + eox[e] - pa.x;
        const float dy = P[e].y + eoy[e] - pa.y;
        const float dz = P[e].z + eoz[e] - pa.z;
        const int   tj = __float_as_int(P[e].w);

        const float r2 = dx * dx + dy * dy + dz * dz;
        const float r  = fsqrt_approx(r2);

        const float h = (vld[e] && (r < RC))
                      ? (0.25f * fcos_approx(r * (PI_F / RC)) + 0.25f)
                      : 0.0f;

        const float u  = r * (1.0f / RC) - 1.0f;
        const float x  = 2.0f * u * u - 1.0f;
        const float tw = x + x;

        float T[8];
        T[1] = x;
        T[2] = tw * x - 1.0f;
        #pragma unroll
        for (int k = 3; k < 8; k++) T[k] = tw * T[k - 1] - T[k - 2];

        #pragma unroll
        for (int t = 0; t < 4; t++) {
            const float wh = (tj == t) ? h : 0.0f;
            G[t][0] += wh;                          // T0 == 1
            #pragma unroll
            for (int k = 1; k < 8; k++) G[t][k] += wh * T[k];
        }
    }

    // ---- full-warp halving butterfly: 32 values over 32 lanes ----
    // After 5 stages (masks 16,8,4,2,1), lane l holds total of v[l].
    float* v = &G[0][0];
    const bool b4 = (lane & 16) != 0;
    const bool b3 = (lane & 8)  != 0;
    const bool b2 = (lane & 4)  != 0;
    const bool b1 = (lane & 2)  != 0;
    const bool b0 = (lane & 1)  != 0;

    float s1[16];
    #pragma unroll
    for (int i = 0; i < 16; i++) {
        const float send = b4 ? v[i] : v[i + 16];
        const float recv = __shfl_xor_sync(0xffffffffu, send, 16);
        s1[i] = (b4 ? v[i + 16] : v[i]) + recv;
    }
    float s2[8];
    #pragma unroll
    for (int i = 0; i < 8; i++) {
        const float send = b3 ? s1[i] : s1[i + 8];
        const float recv = __shfl_xor_sync(0xffffffffu, send, 8);
        s2[i] = (b3 ? s1[i + 8] : s1[i]) + recv;
    }
    float s3[4];
    #pragma unroll
    for (int i = 0; i < 4; i++) {
        const float send = b2 ? s2[i] : s2[i + 4];
        const float recv = __shfl_xor_sync(0xffffffffu, send, 4);
        s3[i] = (b2 ? s2[i + 4] : s2[i]) + recv;
    }
    float s4[2];
    #pragma unroll
    for (int i = 0; i < 2; i++) {
        const float send = b1 ? s3[i] : s3[i + 2];
        const float recv = __shfl_xor_sync(0xffffffffu, send, 2);
        s4[i] = (b1 ? s3[i + 2] : s3[i]) + recv;
    }
    float gv;
    {
        const float send = b0 ? s4[0] : s4[1];
        const float recv = __shfl_xor_sync(0xffffffffu, send, 1);
        gv = (b0 ? s4[1] : s4[0]) + recv;
    }
    // lane l: t = l>>3, k = l&7. Fold the (T_k + 1) constant term:
    // F = G[t][k] + G[t][0]; G[t][0] sits on lane (l & 24).
    const float g0 = __shfl_sync(0xffffffffu, gv, lane & 24);
    const float F  = gv + g0;

    // matvec: lane l holds F(t,k); multiply by c_t[ti][t][k][d] for d=0..7
    const float4* c4p = reinterpret_cast<const float4*>(c_sh);
    const int cbase = (ti * 256 + lane * 8) >> 2;   // float4 index
    const float4 cA = c4p[cbase + 0];
    const float4 cB = c4p[cbase + 1];
    float p[8];
    p[0] = F * cA.x; p[1] = F * cA.y; p[2] = F * cA.z; p[3] = F * cA.w;
    p[4] = F * cB.x; p[5] = F * cB.y; p[6] = F * cB.z; p[7] = F * cB.w;

    // reduce 8 values over 32 lanes; halving stages use masks 4,2,1 so that
    // descriptor index d = lane&7 at the end; masks 8,16 are plain adds.
    float q[4];
    #pragma unroll
    for (int i = 0; i < 4; i++) {
        const float send = b2 ? p[i] : p[i + 4];
        const float recv = __shfl_xor_sync(0xffffffffu, send, 4);
        q[i] = (b2 ? p[i + 4] : p[i]) + recv;
    }
    float rr[2];
    #pragma unroll
    for (int i = 0; i < 2; i++) {
        const float send = b1 ? q[i] : q[i + 2];
        const float recv = __shfl_xor_sync(0xffffffffu, send, 2);
        rr[i] = (b1 ? q[i + 2] : q[i]) + recv;
    }
    float o;
    {
        const float send = b0 ? rr[0] : rr[1];
        const float recv = __shfl_xor_sync(0xffffffffu, send, 1);
        o = (b0 ? rr[1] : rr[0]) + recv;
    }
    o += __shfl_xor_sync(0xffffffffu, o, 8);
    o += __shfl_xor_sync(0xffffffffu, o, 16);

    if (ok && lane < 8)
        out[(long)atom * 8 + lane] = o;   // 32B contiguous per warp
}

extern "C" void kernel_launch(void* const* d_in, const int* in_sizes, int n_in,
                              void* d_out, int out_size) {
    const int*   types = (const int*)  d_in[0];
    const float* pos   = (const float*)d_in[1];
    const int*   nbr   = (const int*)  d_in[2];
    const float* offs  = (const float*)d_in[3];
    const float* ctab  = (const float*)d_in[4];
    float* out = (float*)d_out;

    int n_atoms = in_sizes[0];
    if (n_atoms > MAX_ATOMS) n_atoms = MAX_ATOMS;

    pack_kernel<<<(n_atoms + 255) / 256, 256>>>(types, pos, n_atoms);

    const int atoms_per_block = 8;                 // 8 warps * 1 atom
    const int grid = (n_atoms + atoms_per_block - 1) / atoms_per_block;
    radial_desc_kernel<<<grid, 256>>>(nbr, offs, ctab, out, n_atoms);
}

// round 4
// speedup vs baseline: 1.0135x; 1.0135x over previous
#include <cuda_runtime.h>

#define NN      64
#define RC      8.0f
#define PI_F    3.14159265358979323846f
#define MAX_ATOMS 32768

// packed[i] = (pos.x, pos.y, pos.z, bitcast(type)); slot [n] = dummy (type=-1)
__device__ float4 g_packed[MAX_ATOMS + 1];

static __device__ __forceinline__ float fsqrt_approx(float x) {
    float y; asm("sqrt.approx.f32 %0, %1;" : "=f"(y) : "f"(x)); return y;
}
static __device__ __forceinline__ float fcos_approx(float x) {
    float y; asm("cos.approx.f32 %0, %1;" : "=f"(y) : "f"(x)); return y;
}
static __device__ __forceinline__ unsigned long long pack2(float lo, float hi) {
    unsigned long long r;
    asm("mov.b64 %0, {%1, %2};" : "=l"(r) : "f"(lo), "f"(hi));
    return r;
}
static __device__ __forceinline__ void fma2(unsigned long long& d,
                                            unsigned long long a,
                                            unsigned long long b) {
    asm("fma.rn.f32x2 %0, %1, %2, %0;" : "+l"(d) : "l"(a), "l"(b));
}
static __device__ __forceinline__ void unpack2(unsigned long long v, float& lo, float& hi) {
    asm("mov.b64 {%0, %1}, %2;" : "=f"(lo), "=f"(hi) : "l"(v));
}

__global__ void pack_kernel(const int* __restrict__ types,
                            const float* __restrict__ pos, int n)
{
    int i = blockIdx.x * blockDim.x + threadIdx.x;
    if (i < n) {
        float4 p;
        p.x = pos[i * 3 + 0];
        p.y = pos[i * 3 + 1];
        p.z = pos[i * 3 + 2];
        p.w = __int_as_float(types[i]);
        g_packed[i] = p;
    }
    if (i == n)
        g_packed[n] = make_float4(0.0f, 0.0f, 0.0f, __int_as_float(-1));
}

// 2 atoms per warp (16 lanes each), 4 edges per lane. 128-thr blocks, 8 atoms/block.
// Packed f32x2 per-type Chebyshev accumulators Gp[4][4] (= G[4][8] floats),
// 4-stage halving butterfly over the 16-lane group, transposed-c_table matvec,
// distributing reduce so descriptor d lands on lane (L&7).
__global__ __launch_bounds__(128, 8) void radial_desc_kernel(
    const int*   __restrict__ nbr,
    const float* __restrict__ offs,
    const float* __restrict__ ctab,
    float*       __restrict__ out,
    int n_atoms)
{
    // transposed: c_sh[tt*64 + k*8 + d] = ctab[tt*64 + d*8 + k]
    __shared__ float c_sh[1024];
    for (int i = threadIdx.x; i < 1024; i += 128) {
        const int d = (i >> 3) & 7;
        const int k = i & 7;
        c_sh[(i & ~63) | (k << 3) | d] = ctab[i];
    }
    __syncthreads();

    const int lane = threadIdx.x & 31;
    const int warp = threadIdx.x >> 5;
    const int L    = lane & 15;     // lane within atom group
    const int grp  = lane >> 4;     // atom slot within warp

    const int atom = blockIdx.x * 8 + warp * 2 + grp;
    const bool ok  = (atom < n_atoms);
    const int a    = ok ? atom : 0;

    const float4 pa = g_packed[a];
    const int    ti = __float_as_int(pa.w);

    // lane owns edges 4L .. 4L+3
    const int4 nv = __ldcs(reinterpret_cast<const int4*>(nbr) + (long)a * 16 + L);
    const float4* ob = reinterpret_cast<const float4*>(offs) + (long)a * 48 + L * 3;
    const float4 f0 = __ldcs(ob + 0);
    const float4 f1 = __ldcs(ob + 1);
    const float4 f2 = __ldcs(ob + 2);

    // invalid (-1) -> dummy slot with type -1 (matches no type, finite coords)
    const int i0 = (nv.x < 0) ? n_atoms : nv.x;
    const int i1 = (nv.y < 0) ? n_atoms : nv.y;
    const int i2 = (nv.z < 0) ? n_atoms : nv.z;
    const int i3 = (nv.w < 0) ? n_atoms : nv.w;

    const float4 P0 = g_packed[i0];
    const float4 P1 = g_packed[i1];
    const float4 P2 = g_packed[i2];
    const float4 P3 = g_packed[i3];

    unsigned long long Gp[16];     // Gp[t*4+i] = {G[t][2i], G[t][2i+1]}
    #pragma unroll
    for (int i = 0; i < 16; i++) Gp[i] = 0ull;

    const float4 P[4]  = { P0, P1, P2, P3 };
    const float eox[4] = { f0.x, f0.w, f1.z, f2.y };
    const float eoy[4] = { f0.y, f1.x, f1.w, f2.z };
    const float eoz[4] = { f0.z, f1.y, f2.x, f2.w };

    #pragma unroll
    for (int e = 0; e < 4; e++) {
        const float dx = P[e].x + eox[e] - pa.x;
        const float dy = P[e].y + eoy[e] - pa.y;
        const float dz = P[e].z + eoz[e] - pa.z;
        const int   tj = __float_as_int(P[e].w);

        const float r2 = dx * dx + dy * dy + dz * dz;
        const float r  = fsqrt_approx(r2);

        float h = 0.25f * fcos_approx(r * (PI_F / RC)) + 0.25f;
        h = (r < RC) ? h : 0.0f;

        const float u  = r * (1.0f / RC) - 1.0f;
        const float x  = 2.0f * u * u - 1.0f;
        const float tw = x + x;
        const float T2 = tw * x  - 1.0f;
        const float T3 = tw * T2 - x;
        const float T4 = tw * T3 - T2;
        const float T5 = tw * T4 - T3;
        const float T6 = tw * T5 - T4;
        const float T7 = tw * T6 - T5;

        const unsigned long long V0 = pack2(1.0f, x);   // T0, T1
        const unsigned long long V1 = pack2(T2, T3);
        const unsigned long long V2 = pack2(T4, T5);
        const unsigned long long V3 = pack2(T6, T7);
        const unsigned long long H  = pack2(h, h);

        #pragma unroll
        for (int t = 0; t < 4; t++) {
            const unsigned long long W = (tj == t) ? H : 0ull;
            fma2(Gp[t * 4 + 0], W, V0);
            fma2(Gp[t * 4 + 1], W, V1);
            fma2(Gp[t * 4 + 2], W, V2);
            fma2(Gp[t * 4 + 3], W, V3);
        }
    }

    // unpack to v[32], v[t*8+k]
    float v[32];
    #pragma unroll
    for (int i = 0; i < 16; i++) unpack2(Gp[i], v[i * 2], v[i * 2 + 1]);

    const bool b3 = (lane & 8) != 0;
    const bool b2 = (lane & 4) != 0;
    const bool b1 = (lane & 2) != 0;
    const bool b0 = (lane & 1) != 0;

    // 4-stage halving butterfly over the 16-lane group:
    // lane L ends with totals of value indices {2L, 2L+1} (t=L>>2, k=2(L&3)+{0,1})
    float w1[16];
    #pragma unroll
    for (int i = 0; i < 16; i++) {
        const float send = b3 ? v[i] : v[i + 16];
        const float recv = __shfl_xor_sync(0xffffffffu, send, 8);
        w1[i] = (b3 ? v[i + 16] : v[i]) + recv;
    }
    float w2[8];
    #pragma unroll
    for (int i = 0; i < 8; i++) {
        const float send = b2 ? w1[i] : w1[i + 8];
        const float recv = __shfl_xor_sync(0xffffffffu, send, 4);
        w2[i] = (b2 ? w1[i + 8] : w1[i]) + recv;
    }
    float w3[4];
    #pragma unroll
    for (int i = 0; i < 4; i++) {
        const float send = b1 ? w2[i] : w2[i + 4];
        const float recv = __shfl_xor_sync(0xffffffffu, send, 2);
        w3[i] = (b1 ? w2[i + 4] : w2[i]) + recv;
    }
    float ve, vo;
    {
        const float send = b0 ? w3[0] : w3[2];
        const float recv = __shfl_xor_sync(0xffffffffu, send, 1);
        ve = (b0 ? w3[2] : w3[0]) + recv;
    }
    {
        const float send = b0 ? w3[1] : w3[3];
        const float recv = __shfl_xor_sync(0xffffffffu, send, 1);
        vo = (b0 ? w3[3] : w3[1]) + recv;
    }

    // fold the (T_k + 1) constant term: F = G[t][k] + G[t][0]
    // G[t][0] = even value of lane (group | t*4)
    const int src = (lane & 16) | ((L >> 2) << 2);
    const float g0 = __shfl_sync(0xffffffffu, ve, src);
    const float Fe = ve + g0;
    const float Fo = vo + g0;

    // matvec: lane L holds F(t, k0), F(t, k0+1); rows k0, k0+1 of transposed c
    const int t  = L >> 2;
    const int k0 = (L & 3) * 2;
    const float4* c4 = reinterpret_cast<const float4*>(c_sh);
    const int rb = ((ti * 4 + t) * 8 + k0) * 2;   // float4 index of row k0
    const float4 cA0 = c4[rb + 0];
    const float4 cA1 = c4[rb + 1];
    const float4 cB0 = c4[rb + 2];
    const float4 cB1 = c4[rb + 3];

    float p[8];
    p[0] = Fe * cA0.x + Fo * cB0.x;
    p[1] = Fe * cA0.y + Fo * cB0.y;
    p[2] = Fe * cA0.z + Fo * cB0.z;
    p[3] = Fe * cA0.w + Fo * cB0.w;
    p[4] = Fe * cA1.x + Fo * cB1.x;
    p[5] = Fe * cA1.y + Fo * cB1.y;
    p[6] = Fe * cA1.z + Fo * cB1.z;
    p[7] = Fe * cA1.w + Fo * cB1.w;

    // distributing reduce of 8 values over the 16-lane group; d ends on lane L&7
    float q[4];
    #pragma unroll
    for (int i = 0; i < 4; i++) {
        const float send = b2 ? p[i] : p[i + 4];
        const float recv = __shfl_xor_sync(0xffffffffu, send, 4);
        q[i] = (b2 ? p[i + 4] : p[i]) + recv;
    }
    float rr[2];
    #pragma unroll
    for (int i = 0; i < 2; i++) {
        const float send = b1 ? q[i] : q[i + 2];
        const float recv = __shfl_xor_sync(0xffffffffu, send, 2);
        rr[i] = (b1 ? q[i + 2] : q[i]) + recv;
    }
    float o;
    {
        const float send = b0 ? rr[0] : rr[1];
        const float recv = __shfl_xor_sync(0xffffffffu, send, 1);
        o = (b0 ? rr[1] : rr[0]) + recv;
    }
    o += __shfl_xor_sync(0xffffffffu, o, 8);   // combine the two 8-lane halves

    if (ok && L < 8)
        out[(long)atom * 8 + L] = o;           // 64B contiguous per warp
}

extern "C" void kernel_launch(void* const* d_in, const int* in_sizes, int n_in,
                              void* d_out, int out_size) {
    const int*   types = (const int*)  d_in[0];
    const float* pos   = (const float*)d_in[1];
    const int*   nbr   = (const int*)  d_in[2];
    const float* offs  = (const float*)d_in[3];
    const float* ctab  = (const float*)d_in[4];
    float* out = (float*)d_out;

    int n_atoms = in_sizes[0];
    if (n_atoms > MAX_ATOMS) n_atoms = MAX_ATOMS;

    pack_kernel<<<(n_atoms + 1 + 255) / 256, 256>>>(types, pos, n_atoms);

    const int atoms_per_block = 8;                 // 4 warps * 2 atoms
    const int grid = (n_atoms + atoms_per_block - 1) / atoms_per_block;
    radial_desc_kernel<<<grid, 128>>>(nbr, offs, ctab, out, n_atoms);
}